// round 14
// baseline (speedup 1.0000x reference)
#include <cuda_runtime.h>

// CombinedLoraA: out[c, r] = sum_k x[xids[c*64+r], k] * A[wids[c], k, r]
//   x:[512,1,4096] f32  xids:[20480] i32  wids:[320] i32  A:[80,4096,64] f32
//   out:[320,1,64] f32
//
// R13 = R10 (verified 51.3us) + ONLY the parallel-setup change:
//   setup:  13 blocks x 32 thr, one rank/seg task per thread (9.1 -> ~2us).
//   main:   R3/R10's measured-best 40.7us config, byte-identical.
//   reduce: R10's kr-parallel version (measured ~1.5us), unchanged.
// (Dual-c ILP deferred to next round — isolating changes after two infra
//  failures on the combined source.)

constexpr int KDIM   = 4096;
constexpr int RANK   = 64;
constexpr int CDIM   = 320;
constexpr int NADAPT = 80;
constexpr int NTOK   = 512;
constexpr int KR     = 32;               // k per range
constexpr int NKR    = KDIM / KR;        // 128
constexpr int ASPLIT = 7;                // grid 128*7 = 896 CTAs
constexpr int NTHR   = 256;
constexpr int NPAIR  = CDIM * RANK;      // 20480

constexpr int SMEM_BYTES = NTOK * KR * 4            // x slice (64 KB)
                         + CDIM * 4                 // perm
                         + (NADAPT + 1) * 4;        // seg

__device__ float g_scratch[NKR * NPAIR];            // 10.5 MB k-partials
__device__ int   g_perm[CDIM];
__device__ int   g_seg[NADAPT + 1];

// ---- setup: 401 tasks over 13 single-warp blocks ----
constexpr int STASKS  = CDIM + NADAPT + 1;          // 401
constexpr int SBLOCKS = (STASKS + 31) / 32;         // 13

__global__ __launch_bounds__(32) void setup_kernel(const int* __restrict__ wids)
{
    __shared__ int wid_s[CDIM];
    const int tid = threadIdx.x;
    for (int i = tid; i < CDIM; i += 32) wid_s[i] = wids[i];
    __syncthreads();

    const int id = blockIdx.x * 32 + tid;
    if (id < CDIM) {                      // rank of (wid, c) -> perm slot
        const int w = wid_s[id];
        int pos = 0;
#pragma unroll 16
        for (int c2 = 0; c2 < CDIM; ++c2) {
            const int w2 = wid_s[c2];
            pos += (w2 < w) || (w2 == w && c2 < id);
        }
        g_perm[pos] = id;
    } else if (id < STASKS) {             // segment start for adapter wt
        const int wt = id - CDIM;
        int s = 0;
#pragma unroll 16
        for (int c2 = 0; c2 < CDIM; ++c2) s += (wid_s[c2] < wt);
        g_seg[wt] = s;
    }
}

// ---- main: one CTA = (k-range, adapter-slot) ----
__global__ __launch_bounds__(NTHR, 3) void lora_main(
    const float* __restrict__ x,
    const int*   __restrict__ xids,
    const float* __restrict__ A)
{
    extern __shared__ float smem[];
    float4* xs4    = reinterpret_cast<float4*>(smem);           // 512 rows x 8 f4 slots
    int*    perm_s = reinterpret_cast<int*>(smem + NTOK * KR);
    int*    seg_s  = perm_s + CDIM;

    const int tid   = threadIdx.x;
    const int kr0   = blockIdx.x * KR;
    const int aslot = blockIdx.y;

    // stage x k-range for ALL 512 rows; slot = k4 ^ (row & 7)
    for (int i = tid; i < NTOK * 8; i += NTHR) {
        const int row = i >> 3, k4 = i & 7;
        const float4 v = *reinterpret_cast<const float4*>(
            x + (size_t)row * KDIM + kr0 + k4 * 4);
        xs4[row * 8 + (k4 ^ (row & 7))] = v;
    }
    for (int i = tid; i < CDIM; i += NTHR)       perm_s[i] = g_perm[i];
    for (int i = tid; i < NADAPT + 1; i += NTHR) seg_s[i]  = g_seg[i];
    __syncthreads();

    const int r = tid & 63;          // rank index (lane-contiguous)
    const int g = tid >> 6;          // 4 independent thread-groups
    const int w_lo = (aslot * NADAPT) / ASPLIT;
    const int w_hi = ((aslot + 1) * NADAPT) / ASPLIT;

    float* __restrict__ scr = g_scratch + (size_t)blockIdx.x * NPAIR;

    for (int w = w_lo + g; w < w_hi; w += 4) {
        const int lo = seg_s[w], hi = seg_s[w + 1];
        if (lo >= hi) continue;

        // A[w, kr0..kr0+32, r] -> 32 registers (coalesced over r)
        float a[KR];
        const float* __restrict__ Ap = A + ((size_t)w * KDIM + kr0) * RANK + r;
#pragma unroll
        for (int j = 0; j < KR; ++j) a[j] = Ap[j * RANK];

        // software-pipelined token fetch (1 ahead)
        int ci = lo;
        int c  = perm_s[ci];
        int t  = xids[c * 64 + r];
        while (ci < hi) {
            const int c_cur = c, t_cur = t;
            ++ci;
            if (ci < hi) { c = perm_s[ci]; t = xids[c * 64 + r]; }

            const int s = t_cur & 7;
            const float4* __restrict__ xrow = xs4 + t_cur * 8;
            float acc0 = 0.f, acc1 = 0.f, acc2 = 0.f, acc3 = 0.f;
#pragma unroll
            for (int k4 = 0; k4 < 8; ++k4) {
                const float4 xv = xrow[k4 ^ s];
                acc0 = fmaf(a[k4 * 4 + 0], xv.x, acc0);
                acc1 = fmaf(a[k4 * 4 + 1], xv.y, acc1);
                acc2 = fmaf(a[k4 * 4 + 2], xv.z, acc2);
                acc3 = fmaf(a[k4 * 4 + 3], xv.w, acc3);
            }
            scr[c_cur * 64 + r] = (acc0 + acc1) + (acc2 + acc3);
        }
    }
}

// ---- reduce: 640 blocks; block = 8 kr-lanes x 32 pairs; MLP-16/thread ----
__global__ __launch_bounds__(256) void reduce_kernel(float* __restrict__ out)
{
    __shared__ float part[256];
    const int tid    = threadIdx.x;
    const int plocal = tid & 31;                  // pair within block
    const int klane  = tid >> 5;                  // 0..7 (warp-uniform)
    const int pair   = blockIdx.x * 32 + plocal;

    const float* __restrict__ base =
        g_scratch + (size_t)(klane * 16) * NPAIR + pair;

    float s[16];
#pragma unroll
    for (int i = 0; i < 16; ++i) s[i] = base[(size_t)i * NPAIR];   // MLP 16
    float t0 = ((s[0]+s[1])+(s[2]+s[3])) + ((s[4]+s[5])+(s[6]+s[7]));
    float t1 = ((s[8]+s[9])+(s[10]+s[11])) + ((s[12]+s[13])+(s[14]+s[15]));
    part[klane * 32 + plocal] = t0 + t1;
    __syncthreads();
    if (tid < 32) {
        float r0 = part[tid]       + part[32 + tid];
        float r1 = part[64 + tid]  + part[96 + tid];
        float r2 = part[128 + tid] + part[160 + tid];
        float r3 = part[192 + tid] + part[224 + tid];
        out[blockIdx.x * 32 + tid] = (r0 + r1) + (r2 + r3);
    }
}

extern "C" void kernel_launch(void* const* d_in, const int* in_sizes, int n_in,
                              void* d_out, int out_size)
{
    const float* x    = (const float*)d_in[0];
    const int*   xids = (const int*)  d_in[1];
    const int*   wids = (const int*)  d_in[2];
    const float* A    = (const float*)d_in[3];
    float*       out  = (float*)d_out;

    cudaFuncSetAttribute(lora_main,
                         cudaFuncAttributeMaxDynamicSharedMemorySize, SMEM_BYTES);

    setup_kernel<<<SBLOCKS, 32>>>(wids);
    lora_main<<<dim3(NKR, ASPLIT), NTHR, SMEM_BYTES>>>(x, xids, A);
    reduce_kernel<<<NPAIR / 32, 256>>>(out);
}

// round 16
// speedup vs baseline: 1.1374x; 1.1374x over previous
#include <cuda_runtime.h>

// CombinedLoraA: out[c, r] = sum_k x[xids[c*64+r], k] * A[wids[c], k, r]
//   x:[512,1,4096] f32  xids:[20480] i32  wids:[320] i32  A:[80,4096,64] f32
//   out:[320,1,64] f32
//
// R15: R13's verified main core (single-c visit loop, 40.7us) + in-main O(N)
// adapter grouping (smem histogram -> prefix -> atomic scatter; replaces the
// setup LAUNCH whose ~9.5us floor R13 measured). Dual-c ILP intentionally
// EXCLUDED this round: all three container failures carried it; isolating.
//   reduce: R10's kr-parallel version (measured ~1.5us), unchanged.
// Segment-internal perm order is atomic-nondeterministic but each c writes
// only its own scr slot -> output invariant.

constexpr int KDIM   = 4096;
constexpr int RANK   = 64;
constexpr int CDIM   = 320;
constexpr int NADAPT = 80;
constexpr int NTOK   = 512;
constexpr int KR     = 32;               // k per range
constexpr int NKR    = KDIM / KR;        // 128
constexpr int ASPLIT = 7;                // grid 128*7 = 896 CTAs
constexpr int NTHR   = 256;
constexpr int NPAIR  = CDIM * RANK;      // 20480

constexpr int SMEM_BYTES = NTOK * KR * 4            // x slice (64 KB)
                         + CDIM * 4                 // perm
                         + (NADAPT + 1) * 4         // seg
                         + NADAPT * 4               // hist
                         + NADAPT * 4;              // ofs   -> ~67 KB

__device__ float g_scratch[NKR * NPAIR];            // 10.5 MB k-partials

// ---- main: one CTA = (k-range, adapter-slot) ----
__global__ __launch_bounds__(NTHR, 3) void lora_main(
    const float* __restrict__ x,
    const int*   __restrict__ xids,
    const int*   __restrict__ wids,
    const float* __restrict__ A)
{
    extern __shared__ float smem[];
    float4* xs4    = reinterpret_cast<float4*>(smem);           // 512 rows x 8 f4 slots
    int*    perm_s = reinterpret_cast<int*>(smem + NTOK * KR);
    int*    seg_s  = perm_s + CDIM;                             // [NADAPT+1]
    int*    hist_s = seg_s + (NADAPT + 1);                      // [NADAPT]
    int*    ofs_s  = hist_s + NADAPT;                           // [NADAPT]

    const int tid   = threadIdx.x;
    const int kr0   = blockIdx.x * KR;
    const int aslot = blockIdx.y;

    if (tid < NADAPT) hist_s[tid] = 0;
    __syncthreads();

    // stage x k-range for ALL 512 rows; slot = k4 ^ (row & 7)
    for (int i = tid; i < NTOK * 8; i += NTHR) {
        const int row = i >> 3, k4 = i & 7;
        const float4 v = *reinterpret_cast<const float4*>(
            x + (size_t)row * KDIM + kr0 + k4 * 4);
        xs4[row * 8 + (k4 ^ (row & 7))] = v;
    }
    // histogram of wids (O(N), spread atomics)
    const int w0 = wids[tid];
    const int w1 = (tid < CDIM - NTHR) ? wids[NTHR + tid] : -1;
    atomicAdd(&hist_s[w0], 1);
    if (w1 >= 0) atomicAdd(&hist_s[w1], 1);
    __syncthreads();

    // prefix counts -> seg; copy to running offsets
    if (tid < NADAPT + 1) {
        int s = 0;
        for (int w2 = 0; w2 < NADAPT; ++w2) s += (w2 < tid) ? hist_s[w2] : 0;
        seg_s[tid] = s;
        if (tid < NADAPT) ofs_s[tid] = s;
    }
    __syncthreads();

    // scatter c's into perm (order within segment irrelevant)
    {
        int pos = atomicAdd(&ofs_s[w0], 1);
        perm_s[pos] = tid;
        if (w1 >= 0) {
            pos = atomicAdd(&ofs_s[w1], 1);
            perm_s[pos] = NTHR + tid;
        }
    }
    __syncthreads();

    const int r = tid & 63;          // rank index (lane-contiguous)
    const int g = tid >> 6;          // 4 independent thread-groups
    const int w_lo = (aslot * NADAPT) / ASPLIT;
    const int w_hi = ((aslot + 1) * NADAPT) / ASPLIT;

    float* __restrict__ scr = g_scratch + (size_t)blockIdx.x * NPAIR;

    for (int w = w_lo + g; w < w_hi; w += 4) {
        const int lo = seg_s[w], hi = seg_s[w + 1];
        if (lo >= hi) continue;

        // A[w, kr0..kr0+32, r] -> 32 registers (coalesced over r)
        float a[KR];
        const float* __restrict__ Ap = A + ((size_t)w * KDIM + kr0) * RANK + r;
#pragma unroll
        for (int j = 0; j < KR; ++j) a[j] = Ap[j * RANK];

        // software-pipelined token fetch (1 ahead) — R13-verified loop
        int ci = lo;
        int c  = perm_s[ci];
        int t  = xids[c * 64 + r];
        while (ci < hi) {
            const int c_cur = c, t_cur = t;
            ++ci;
            if (ci < hi) { c = perm_s[ci]; t = xids[c * 64 + r]; }

            const int s = t_cur & 7;
            const float4* __restrict__ xrow = xs4 + t_cur * 8;
            float acc0 = 0.f, acc1 = 0.f, acc2 = 0.f, acc3 = 0.f;
#pragma unroll
            for (int k4 = 0; k4 < 8; ++k4) {
                const float4 xv = xrow[k4 ^ s];
                acc0 = fmaf(a[k4 * 4 + 0], xv.x, acc0);
                acc1 = fmaf(a[k4 * 4 + 1], xv.y, acc1);
                acc2 = fmaf(a[k4 * 4 + 2], xv.z, acc2);
                acc3 = fmaf(a[k4 * 4 + 3], xv.w, acc3);
            }
            scr[c_cur * 64 + r] = (acc0 + acc1) + (acc2 + acc3);
        }
    }
}

// ---- reduce: 640 blocks; block = 8 kr-lanes x 32 pairs; MLP-16/thread ----
__global__ __launch_bounds__(256) void reduce_kernel(float* __restrict__ out)
{
    __shared__ float part[256];
    const int tid    = threadIdx.x;
    const int plocal = tid & 31;                  // pair within block
    const int klane  = tid >> 5;                  // 0..7 (warp-uniform)
    const int pair   = blockIdx.x * 32 + plocal;

    const float* __restrict__ base =
        g_scratch + (size_t)(klane * 16) * NPAIR + pair;

    float s[16];
#pragma unroll
    for (int i = 0; i < 16; ++i) s[i] = base[(size_t)i * NPAIR];   // MLP 16
    float t0 = ((s[0]+s[1])+(s[2]+s[3])) + ((s[4]+s[5])+(s[6]+s[7]));
    float t1 = ((s[8]+s[9])+(s[10]+s[11])) + ((s[12]+s[13])+(s[14]+s[15]));
    part[klane * 32 + plocal] = t0 + t1;
    __syncthreads();
    if (tid < 32) {
        float r0 = part[tid]       + part[32 + tid];
        float r1 = part[64 + tid]  + part[96 + tid];
        float r2 = part[128 + tid] + part[160 + tid];
        float r3 = part[192 + tid] + part[224 + tid];
        out[blockIdx.x * 32 + tid] = (r0 + r1) + (r2 + r3);
    }
}

extern "C" void kernel_launch(void* const* d_in, const int* in_sizes, int n_in,
                              void* d_out, int out_size)
{
    const float* x    = (const float*)d_in[0];
    const int*   xids = (const int*)  d_in[1];
    const int*   wids = (const int*)  d_in[2];
    const float* A    = (const float*)d_in[3];
    float*       out  = (float*)d_out;

    cudaFuncSetAttribute(lora_main,
                         cudaFuncAttributeMaxDynamicSharedMemorySize, SMEM_BYTES);

    lora_main<<<dim3(NKR, ASPLIT), NTHR, SMEM_BYTES>>>(x, xids, wids, A);
    reduce_kernel<<<NPAIR / 32, 256>>>(out);
}

// round 17
// speedup vs baseline: 1.1740x; 1.0322x over previous
#include <cuda_runtime.h>

// CombinedLoraA: out[c, r] = sum_k x[xids[c*64+r], k] * A[wids[c], k, r]
//   x:[512,1,4096] f32  xids:[20480] i32  wids:[320] i32  A:[80,4096,64] f32
//   out:[320,1,64] f32
//
// R16 = R15 (verified 45.2us) + 2-tile accumulation:
//   main: one CTA = (kr-slice, adapter-slot) now covers TWO k-tiles
//         (kr0 and kr0+2048) into one scratch slice (tile0: scr=acc,
//         tile1: scr+=acc; same CTA owns the slot -> race-free, fixed
//         order -> deterministic). Grid 64x7=448 CTAs ~= 1.01 waves @3/SM.
//         In-main O(N) grouping + single-c visit loop unchanged (R15).
//   reduce: depth 64 (scratch halved to 5.25MB) -> ~3.5us vs 6.

constexpr int KDIM   = 4096;
constexpr int RANK   = 64;
constexpr int CDIM   = 320;
constexpr int NADAPT = 80;
constexpr int NTOK   = 512;
constexpr int KR     = 32;               // k per tile
constexpr int NSLICE = 64;               // scratch slices (2 tiles each)
constexpr int HALFK  = KDIM / 2;         // 2048
constexpr int ASPLIT = 7;                // grid 64*7 = 448 CTAs
constexpr int NTHR   = 256;
constexpr int NPAIR  = CDIM * RANK;      // 20480

constexpr int SMEM_BYTES = NTOK * KR * 4            // x slice (64 KB)
                         + CDIM * 4                 // perm
                         + (NADAPT + 1) * 4         // seg
                         + NADAPT * 4               // hist
                         + NADAPT * 4;              // ofs   -> ~67 KB

__device__ float g_scratch[NSLICE * NPAIR];         // 5.25 MB k-partials

// ---- main: one CTA = (kr-slice, adapter-slot), two k-tiles ----
__global__ __launch_bounds__(NTHR, 3) void lora_main(
    const float* __restrict__ x,
    const int*   __restrict__ xids,
    const int*   __restrict__ wids,
    const float* __restrict__ A)
{
    extern __shared__ float smem[];
    float4* xs4    = reinterpret_cast<float4*>(smem);           // 512 rows x 8 f4 slots
    int*    perm_s = reinterpret_cast<int*>(smem + NTOK * KR);
    int*    seg_s  = perm_s + CDIM;                             // [NADAPT+1]
    int*    hist_s = seg_s + (NADAPT + 1);                      // [NADAPT]
    int*    ofs_s  = hist_s + NADAPT;                           // [NADAPT]

    const int tid   = threadIdx.x;
    const int aslot = blockIdx.y;

    if (tid < NADAPT) hist_s[tid] = 0;
    __syncthreads();

    // ---- O(N) adapter grouping (histogram -> prefix -> atomic scatter) ----
    const int w0 = wids[tid];
    const int w1 = (tid < CDIM - NTHR) ? wids[NTHR + tid] : -1;
    atomicAdd(&hist_s[w0], 1);
    if (w1 >= 0) atomicAdd(&hist_s[w1], 1);
    __syncthreads();

    if (tid < NADAPT + 1) {
        int s = 0;
        for (int w2 = 0; w2 < NADAPT; ++w2) s += (w2 < tid) ? hist_s[w2] : 0;
        seg_s[tid] = s;
        if (tid < NADAPT) ofs_s[tid] = s;
    }
    __syncthreads();

    {
        int pos = atomicAdd(&ofs_s[w0], 1);
        perm_s[pos] = tid;
        if (w1 >= 0) {
            pos = atomicAdd(&ofs_s[w1], 1);
            perm_s[pos] = NTHR + tid;
        }
    }
    // NOTE: no sync here; staging below syncs before perm is consumed.

    const int r = tid & 63;          // rank index (lane-contiguous)
    const int g = tid >> 6;          // 4 independent thread-groups
    const int w_lo = (aslot * NADAPT) / ASPLIT;
    const int w_hi = ((aslot + 1) * NADAPT) / ASPLIT;

    float* __restrict__ scr = g_scratch + (size_t)blockIdx.x * NPAIR;

#pragma unroll
    for (int half = 0; half < 2; ++half) {
        const int kr0 = blockIdx.x * KR + half * HALFK;

        __syncthreads();   // tile buffer free (half 0: grouping also done)

        // stage x k-tile for ALL 512 rows; slot = k4 ^ (row & 7)
        for (int i = tid; i < NTOK * 8; i += NTHR) {
            const int row = i >> 3, k4 = i & 7;
            const float4 v = *reinterpret_cast<const float4*>(
                x + (size_t)row * KDIM + kr0 + k4 * 4);
            xs4[row * 8 + (k4 ^ (row & 7))] = v;
        }
        __syncthreads();

        for (int w = w_lo + g; w < w_hi; w += 4) {
            const int lo = seg_s[w], hi = seg_s[w + 1];
            if (lo >= hi) continue;

            // A[w, kr0..kr0+32, r] -> 32 registers (coalesced over r)
            float a[KR];
            const float* __restrict__ Ap = A + ((size_t)w * KDIM + kr0) * RANK + r;
#pragma unroll
            for (int j = 0; j < KR; ++j) a[j] = Ap[j * RANK];

            // software-pipelined token fetch (1 ahead) — verified loop
            int ci = lo;
            int c  = perm_s[ci];
            int t  = xids[c * 64 + r];
            while (ci < hi) {
                const int c_cur = c, t_cur = t;
                ++ci;
                if (ci < hi) { c = perm_s[ci]; t = xids[c * 64 + r]; }

                const int s = t_cur & 7;
                const float4* __restrict__ xrow = xs4 + t_cur * 8;
                float acc0 = 0.f, acc1 = 0.f, acc2 = 0.f, acc3 = 0.f;
#pragma unroll
                for (int k4 = 0; k4 < 8; ++k4) {
                    const float4 xv = xrow[k4 ^ s];
                    acc0 = fmaf(a[k4 * 4 + 0], xv.x, acc0);
                    acc1 = fmaf(a[k4 * 4 + 1], xv.y, acc1);
                    acc2 = fmaf(a[k4 * 4 + 2], xv.z, acc2);
                    acc3 = fmaf(a[k4 * 4 + 3], xv.w, acc3);
                }
                const float acc = (acc0 + acc1) + (acc2 + acc3);
                if (half == 0) scr[c_cur * 64 + r] = acc;
                else           scr[c_cur * 64 + r] += acc;   // same CTA owns slot
            }
        }
    }
}

// ---- reduce: 640 blocks; block = 8 kr-lanes x 32 pairs; 8 loads/thread ----
__global__ __launch_bounds__(256) void reduce_kernel(float* __restrict__ out)
{
    __shared__ float part[256];
    const int tid    = threadIdx.x;
    const int plocal = tid & 31;                  // pair within block
    const int klane  = tid >> 5;                  // 0..7 (warp-uniform)
    const int pair   = blockIdx.x * 32 + plocal;

    const float* __restrict__ base =
        g_scratch + (size_t)(klane * 8) * NPAIR + pair;

    float s[8];
#pragma unroll
    for (int i = 0; i < 8; ++i) s[i] = base[(size_t)i * NPAIR];   // MLP 8
    part[klane * 32 + plocal] =
        ((s[0] + s[1]) + (s[2] + s[3])) + ((s[4] + s[5]) + (s[6] + s[7]));
    __syncthreads();
    if (tid < 32) {
        float r0 = part[tid]       + part[32 + tid];
        float r1 = part[64 + tid]  + part[96 + tid];
        float r2 = part[128 + tid] + part[160 + tid];
        float r3 = part[192 + tid] + part[224 + tid];
        out[blockIdx.x * 32 + tid] = (r0 + r1) + (r2 + r3);
    }
}

extern "C" void kernel_launch(void* const* d_in, const int* in_sizes, int n_in,
                              void* d_out, int out_size)
{
    const float* x    = (const float*)d_in[0];
    const int*   xids = (const int*)  d_in[1];
    const int*   wids = (const int*)  d_in[2];
    const float* A    = (const float*)d_in[3];
    float*       out  = (float*)d_out;

    cudaFuncSetAttribute(lora_main,
                         cudaFuncAttributeMaxDynamicSharedMemorySize, SMEM_BYTES);

    lora_main<<<dim3(NSLICE, ASPLIT), NTHR, SMEM_BYTES>>>(x, xids, wids, A);
    reduce_kernel<<<NPAIR / 32, 256>>>(out);
}